// round 2
// baseline (speedup 1.0000x reference)
#include <cuda_runtime.h>
#include <math.h>

// ---------------- problem constants (fixed shapes) ----------------
#define NT 10000      // total nodes (4*2500)
#define NE 120000     // edges
#define HCMAX 512     // max hidden width (4 heads * 128)

// ---------------- device scratch (no allocations allowed) ----------------
__device__ float g_XL[NT * HCMAX];   // source transform  x@Wl+bl
__device__ float g_XR[NT * HCMAX];   // target transform  x@Wr+br
__device__ float g_H [NT * HCMAX];   // layer activations
__device__ int   g_deg[NT];
__device__ int   g_start[NT + 1];
__device__ int   g_cursor[NT];
__device__ int   g_csr[NE];          // edge ids grouped by dst

// ---------------- CSR build ----------------
__global__ void k_zero_deg() {
    int i = blockIdx.x * blockDim.x + threadIdx.x;
    if (i < NT) g_deg[i] = 0;
}

__global__ void k_hist(const int* __restrict__ dst) {
    int e = blockIdx.x * blockDim.x + threadIdx.x;
    if (e < NE) atomicAdd(&g_deg[dst[e]], 1);
}

__global__ void k_scan() {
    __shared__ int sh[256];
    const int CH = (NT + 255) / 256;  // 40
    int tid = threadIdx.x;
    int base = tid * CH;
    int s = 0;
    for (int i = 0; i < CH; i++) {
        int n = base + i;
        if (n < NT) s += g_deg[n];
    }
    sh[tid] = s;
    __syncthreads();
    for (int off = 1; off < 256; off <<= 1) {
        int v = (tid >= off) ? sh[tid - off] : 0;
        __syncthreads();
        sh[tid] += v;
        __syncthreads();
    }
    int run = sh[tid] - s;   // exclusive prefix of this chunk
    for (int i = 0; i < CH; i++) {
        int n = base + i;
        if (n < NT) {
            g_start[n]  = run;
            g_cursor[n] = run;
            run += g_deg[n];
        }
    }
    if (tid == 255) g_start[NT] = sh[255];
}

__global__ void k_scatter(const int* __restrict__ dst) {
    int e = blockIdx.x * blockDim.x + threadIdx.x;
    if (e < NE) {
        int p = atomicAdd(&g_cursor[dst[e]], 1);
        g_csr[p] = e;
    }
}

// ---------------- dual GEMM:  C0 = A@B0+bias0,  C1 = A@B1+bias1 ----------------
// 128x128 tile, BK=16, 256 threads, 8x8 micro-tile (4+4 split at +64 in m and n),
// double-buffered shared memory. blockIdx.z selects (B0,C0)/(B1,C1).
__global__ void __launch_bounds__(256, 1)
k_gemm_dual(const float* __restrict__ A,
            const float* __restrict__ B0, const float* __restrict__ bias0, float* __restrict__ C0,
            const float* __restrict__ B1, const float* __restrict__ bias1, float* __restrict__ C1,
            int M, int N, int K) {
    constexpr int BM = 128, BN = 128, BK = 16, PAD = 4;
    const float* B    = blockIdx.z ? B1    : B0;
    const float* bias = blockIdx.z ? bias1 : bias0;
    float*       C    = blockIdx.z ? C1    : C0;

    __shared__ float As[2][BK][BM + PAD];
    __shared__ float Bs[2][BK][BN];

    const int tid  = threadIdx.x;
    const int tx   = tid & 15;        // 0..15
    const int ty   = tid >> 4;        // 0..15
    const int row0 = blockIdx.y * BM;
    const int col0 = blockIdx.x * BN;

    // A-tile loads: thread handles rows (ar, ar+64), cols [k0+ac, k0+ac+3]
    const int ar = tid >> 2;          // 0..63
    const int ac = (tid & 3) << 2;    // 0,4,8,12
    // B-tile loads: thread handles rows (brr, brr+8), col4 group
    const int brr = tid >> 5;         // 0..7
    const int bcc = (tid & 31) << 2;  // 0..124

    const float* Arow0 = A + (size_t)(row0 + ar)      * K;
    const float* Arow1 = A + (size_t)(row0 + ar + 64) * K;
    const bool   aok0  = (row0 + ar)      < M;
    const bool   aok1  = (row0 + ar + 64) < M;

    float acc[2][2][4][4] = {};       // [rowhalf][colhalf][i][j]

    const int nsteps = K / BK;

    // --- prologue: stage 0 ---
    {
        float4 av0 = make_float4(0.f,0.f,0.f,0.f), av1 = av0;
        if (aok0) av0 = *(const float4*)&Arow0[ac];
        if (aok1) av1 = *(const float4*)&Arow1[ac];
        float4 bv0 = *(const float4*)&B[(size_t)(brr    ) * N + col0 + bcc];
        float4 bv1 = *(const float4*)&B[(size_t)(brr + 8) * N + col0 + bcc];
        As[0][ac+0][ar] = av0.x; As[0][ac+1][ar] = av0.y; As[0][ac+2][ar] = av0.z; As[0][ac+3][ar] = av0.w;
        As[0][ac+0][ar+64] = av1.x; As[0][ac+1][ar+64] = av1.y; As[0][ac+2][ar+64] = av1.z; As[0][ac+3][ar+64] = av1.w;
        *(float4*)&Bs[0][brr][bcc]     = bv0;
        *(float4*)&Bs[0][brr + 8][bcc] = bv1;
    }
    __syncthreads();

    for (int s = 0; s < nsteps; s++) {
        const int cur = s & 1;
        const bool more = (s + 1) < nsteps;

        float4 pa0, pa1, pb0, pb1;
        if (more) {
            const int kn = (s + 1) * BK;
            pa0 = make_float4(0.f,0.f,0.f,0.f); pa1 = pa0;
            if (aok0) pa0 = *(const float4*)&Arow0[kn + ac];
            if (aok1) pa1 = *(const float4*)&Arow1[kn + ac];
            pb0 = *(const float4*)&B[(size_t)(kn + brr    ) * N + col0 + bcc];
            pb1 = *(const float4*)&B[(size_t)(kn + brr + 8) * N + col0 + bcc];
        }

#pragma unroll
        for (int k = 0; k < BK; k++) {
            float a[2][4], b[2][4];
            *(float4*)a[0] = *(const float4*)&As[cur][k][ty * 4];
            *(float4*)a[1] = *(const float4*)&As[cur][k][ty * 4 + 64];
            *(float4*)b[0] = *(const float4*)&Bs[cur][k][tx * 4];
            *(float4*)b[1] = *(const float4*)&Bs[cur][k][tx * 4 + 64];
#pragma unroll
            for (int rh = 0; rh < 2; rh++)
#pragma unroll
                for (int ch = 0; ch < 2; ch++)
#pragma unroll
                    for (int i = 0; i < 4; i++)
#pragma unroll
                        for (int j = 0; j < 4; j++)
                            acc[rh][ch][i][j] += a[rh][i] * b[ch][j];
        }

        if (more) {
            const int nxt = cur ^ 1;
            As[nxt][ac+0][ar] = pa0.x; As[nxt][ac+1][ar] = pa0.y; As[nxt][ac+2][ar] = pa0.z; As[nxt][ac+3][ar] = pa0.w;
            As[nxt][ac+0][ar+64] = pa1.x; As[nxt][ac+1][ar+64] = pa1.y; As[nxt][ac+2][ar+64] = pa1.z; As[nxt][ac+3][ar+64] = pa1.w;
            *(float4*)&Bs[nxt][brr][bcc]     = pb0;
            *(float4*)&Bs[nxt][brr + 8][bcc] = pb1;
            __syncthreads();
        }
    }

    // --- epilogue: bias + store ---
#pragma unroll
    for (int rh = 0; rh < 2; rh++) {
#pragma unroll
        for (int i = 0; i < 4; i++) {
            int m = row0 + rh * 64 + ty * 4 + i;
            if (m < M) {
#pragma unroll
                for (int ch = 0; ch < 2; ch++) {
                    int cb = col0 + ch * 64 + tx * 4;
                    float4 o;
                    o.x = acc[rh][ch][i][0] + bias[cb + 0];
                    o.y = acc[rh][ch][i][1] + bias[cb + 1];
                    o.z = acc[rh][ch][i][2] + bias[cb + 2];
                    o.w = acc[rh][ch][i][3] + bias[cb + 3];
                    *(float4*)&C[(size_t)m * N + cb] = o;
                }
            }
        }
    }
}

// ---------------- per-dst-node GATv2 aggregation ----------------
template <int H, int C, bool DO_ELU>
__global__ void __launch_bounds__(128)
k_gat_aggregate(const float* __restrict__ ew,
                const int*   __restrict__ srcArr,
                const float* __restrict__ We,
                const float* __restrict__ att,
                const float* __restrict__ bias,
                float* __restrict__ out) {
    constexpr int HC  = H * C;
    constexpr int T   = 128;
    constexpr int VPT = HC / T;       // 4 (H=4,C=128) or 2 (H=1,C=256)
    constexpr int MAXDEG = 1024;

    __shared__ float sh_xr[HC];
    __shared__ float sh_We[HC];
    __shared__ float sh_att[HC];
    __shared__ float sh_l[MAXDEG * H];
    __shared__ float sh_red[4];

    const int nd  = blockIdx.x;
    const int tid = threadIdx.x;
    const int chb = tid * VPT;            // base channel of this thread
    const int h   = chb / C;              // head of this thread

    for (int i = tid; i < HC; i += T) {
        sh_xr[i]  = g_XR[(size_t)nd * HC + i];
        sh_We[i]  = We[i];
        sh_att[i] = att[i];
    }
    __syncthreads();

    int s0  = g_start[nd];
    int deg = g_start[nd + 1] - s0;
    if (deg > MAXDEG) deg = MAXDEG;

    // ---- pass 1: logits ----
    for (int eo = 0; eo < deg; eo++) {
        int   e = g_csr[s0 + eo];
        int   s = srcArr[e];
        float w = ew[e];
        const float* xlrow = &g_XL[(size_t)s * HC + chb];

        float xv[VPT];
        if constexpr (VPT == 4) {
            float4 v = *(const float4*)xlrow;
            xv[0] = v.x; xv[1] = v.y; xv[2] = v.z; xv[3] = v.w;
        } else {
            float2 v = *(const float2*)xlrow;
            xv[0] = v.x; xv[1] = v.y;
        }

        float partial = 0.f;
#pragma unroll
        for (int j = 0; j < VPT; j++) {
            float v = xv[j] + sh_xr[chb + j] + w * sh_We[chb + j];
            v = (v > 0.f) ? v : 0.2f * v;   // leaky_relu(0.2)
            partial += v * sh_att[chb + j];
        }
#pragma unroll
        for (int off = 16; off; off >>= 1)
            partial += __shfl_xor_sync(0xffffffff, partial, off);

        if constexpr (H == 4) {
            if ((tid & 31) == 0) sh_l[eo * H + h] = partial;
        } else {
            if ((tid & 31) == 0) sh_red[tid >> 5] = partial;
            __syncthreads();
            if (tid == 0) sh_l[eo] = sh_red[0] + sh_red[1] + sh_red[2] + sh_red[3];
            __syncthreads();
        }
    }
    __syncthreads();

    // ---- softmax per head ----
    if (tid < H) {
        float m = -INFINITY;
        for (int eo = 0; eo < deg; eo++) m = fmaxf(m, sh_l[eo * H + tid]);
        float ssum = 0.f;
        for (int eo = 0; eo < deg; eo++) {
            float p = expf(sh_l[eo * H + tid] - m);
            sh_l[eo * H + tid] = p;
            ssum += p;
        }
        float inv = 1.f / (ssum + 1e-16f);
        for (int eo = 0; eo < deg; eo++) sh_l[eo * H + tid] *= inv;
    }
    __syncthreads();

    // ---- pass 2: weighted accumulation ----
    float acc[VPT] = {};
    for (int eo = 0; eo < deg; eo++) {
        int   e = g_csr[s0 + eo];
        int   s = srcArr[e];
        float a = sh_l[eo * H + h];
        const float* xlrow = &g_XL[(size_t)s * HC + chb];
        if constexpr (VPT == 4) {
            float4 v = *(const float4*)xlrow;
            acc[0] += a * v.x; acc[1] += a * v.y; acc[2] += a * v.z; acc[3] += a * v.w;
        } else {
            float2 v = *(const float2*)xlrow;
            acc[0] += a * v.x; acc[1] += a * v.y;
        }
    }

#pragma unroll
    for (int j = 0; j < VPT; j++) {
        float o = acc[j] + bias[chb + j];
        if constexpr (DO_ELU) o = (o > 0.f) ? o : expm1f(o);
        out[(size_t)nd * HC + chb + j] = o;
    }
}

// ---------------- launch ----------------
extern "C" void kernel_launch(void* const* d_in, const int* in_sizes, int n_in,
                              void* d_out, int out_size) {
    const float* x   = (const float*)d_in[0];
    const int*   ei  = (const int*)  d_in[1];
    const float* ew  = (const float*)d_in[2];
    const int* src = ei;
    const int* dst = ei + NE;

    const float *Wl[3], *bl[3], *Wr[3], *br[3], *We[3], *att[3], *bias[3];
    for (int l = 0; l < 3; l++) {
        int b = 3 + 7 * l;
        Wl[l]   = (const float*)d_in[b + 0];
        bl[l]   = (const float*)d_in[b + 1];
        Wr[l]   = (const float*)d_in[b + 2];
        br[l]   = (const float*)d_in[b + 3];
        We[l]   = (const float*)d_in[b + 4];
        att[l]  = (const float*)d_in[b + 5];
        bias[l] = (const float*)d_in[b + 6];
    }

    float *dXL, *dXR, *dH;
    cudaGetSymbolAddress((void**)&dXL, g_XL);
    cudaGetSymbolAddress((void**)&dXR, g_XR);
    cudaGetSymbolAddress((void**)&dH,  g_H);
    float* dOut = (float*)d_out;

    // CSR by destination
    k_zero_deg<<<(NT + 255) / 256, 256>>>();
    k_hist    <<<(NE + 255) / 256, 256>>>(dst);
    k_scan    <<<1, 256>>>();
    k_scatter <<<(NE + 255) / 256, 256>>>(dst);

    const int MB = (NT + 127) / 128;   // 79 row tiles

    // ---- layer 0: in 64 -> 4x128 ----
    k_gemm_dual<<<dim3(512 / 128, MB, 2), 256>>>(x,
        Wl[0], bl[0], dXL,  Wr[0], br[0], dXR, NT, 512, 64);
    k_gat_aggregate<4, 128, true><<<NT, 128>>>(ew, src, We[0], att[0], bias[0], dH);

    // ---- layer 1: 512 -> 4x128 ----
    k_gemm_dual<<<dim3(512 / 128, MB, 2), 256>>>(dH,
        Wl[1], bl[1], dXL,  Wr[1], br[1], dXR, NT, 512, 512);
    k_gat_aggregate<4, 128, true><<<NT, 128>>>(ew, src, We[1], att[1], bias[1], dH);

    // ---- layer 2: 512 -> 1x256 (no ELU), writes d_out directly ----
    k_gemm_dual<<<dim3(256 / 128, MB, 2), 256>>>(dH,
        Wl[2], bl[2], dXL,  Wr[2], br[2], dXR, NT, 256, 512);
    k_gat_aggregate<1, 256, false><<<NT, 128>>>(ew, src, We[2], att[2], bias[2], dOut);
}

// round 4
// speedup vs baseline: 1.5870x; 1.5870x over previous
#include <cuda_runtime.h>
#include <cuda_bf16.h>
#include <math.h>
#include <cstdint>

// ---------------- problem constants ----------------
#define NT 10000      // total nodes
#define NE 120000     // edges
#define HCMAX 512

// ---------------- device scratch ----------------
__device__ float g_XL[NT * HCMAX];
__device__ float g_XR[NT * HCMAX];
__device__ float g_H [NT * HCMAX];
__device__ __nv_bfloat16 g_Ah[NT * HCMAX];
__device__ __nv_bfloat16 g_Al[NT * HCMAX];
__device__ __nv_bfloat16 g_Bh[2 * 512 * 512];   // [z][N][K] transposed weights (hi)
__device__ __nv_bfloat16 g_Bl[2 * 512 * 512];   // (lo)
__device__ int   g_deg[NT];
__device__ int   g_start[NT + 1];
__device__ int   g_cursor[NT];
__device__ int   g_csr[NE];

// ---------------- helpers ----------------
__device__ __forceinline__ uint32_t smem_to_u32(const void* p) {
    uint32_t a;
    asm("{ .reg .u64 t; cvta.to.shared.u64 t, %1; cvt.u32.u64 %0, t; }" : "=r"(a) : "l"(p));
    return a;
}
__device__ __forceinline__ void cp16(void* dst, const void* src, int srcsize) {
    uint32_t d = smem_to_u32(dst);
    asm volatile("cp.async.cg.shared.global [%0], [%1], 16, %2;"
                 :: "r"(d), "l"(src), "r"(srcsize) : "memory");
}
__device__ __forceinline__ void ldsm_x4(uint32_t* r, uint32_t addr) {
    asm volatile("ldmatrix.sync.aligned.m8n8.x4.shared.b16 {%0,%1,%2,%3}, [%4];"
                 : "=r"(r[0]), "=r"(r[1]), "=r"(r[2]), "=r"(r[3]) : "r"(addr));
}
__device__ __forceinline__ void mma_bf16(float* c, const uint32_t* a, const uint32_t* b) {
    asm volatile("mma.sync.aligned.m16n8k16.row.col.f32.bf16.bf16.f32 "
                 "{%0,%1,%2,%3}, {%4,%5,%6,%7}, {%8,%9}, {%0,%1,%2,%3};"
                 : "+f"(c[0]), "+f"(c[1]), "+f"(c[2]), "+f"(c[3])
                 : "r"(a[0]), "r"(a[1]), "r"(a[2]), "r"(a[3]), "r"(b[0]), "r"(b[1]));
}

// ---------------- CSR build ----------------
__global__ void k_zero_deg() {
    int i = blockIdx.x * blockDim.x + threadIdx.x;
    if (i < NT) g_deg[i] = 0;
}
__global__ void k_hist(const int* __restrict__ dst) {
    int e = blockIdx.x * blockDim.x + threadIdx.x;
    if (e < NE) atomicAdd(&g_deg[dst[e]], 1);
}
__global__ void k_scan() {
    __shared__ int sh[256];
    const int CH = (NT + 255) / 256;
    int tid = threadIdx.x;
    int base = tid * CH;
    int s = 0;
    for (int i = 0; i < CH; i++) { int n = base + i; if (n < NT) s += g_deg[n]; }
    sh[tid] = s;
    __syncthreads();
    for (int off = 1; off < 256; off <<= 1) {
        int v = (tid >= off) ? sh[tid - off] : 0;
        __syncthreads();
        sh[tid] += v;
        __syncthreads();
    }
    int run = sh[tid] - s;
    for (int i = 0; i < CH; i++) {
        int n = base + i;
        if (n < NT) { g_start[n] = run; g_cursor[n] = run; run += g_deg[n]; }
    }
    if (tid == 255) g_start[NT] = sh[255];
}
__global__ void k_scatter(const int* __restrict__ dst) {
    int e = blockIdx.x * blockDim.x + threadIdx.x;
    if (e < NE) {
        int p = atomicAdd(&g_cursor[dst[e]], 1);
        g_csr[p] = e;
    }
}

// ---------------- fp32 -> bf16 hi/lo split ----------------
__global__ void k_split(const float* __restrict__ in, __nv_bfloat16* __restrict__ hi,
                        __nv_bfloat16* __restrict__ lo, int n) {
    int i = blockIdx.x * blockDim.x + threadIdx.x;
    if (i < n) {
        float v = in[i];
        __nv_bfloat16 h = __float2bfloat16(v);
        hi[i] = h;
        lo[i] = __float2bfloat16(v - __bfloat162float(h));
    }
}
// W [K,N] row-major -> Wt [N,K] split bf16
__global__ void k_splitW(const float* __restrict__ W, __nv_bfloat16* __restrict__ hi,
                         __nv_bfloat16* __restrict__ lo, int K, int N) {
    int i = blockIdx.x * blockDim.x + threadIdx.x;
    if (i < N * K) {
        int n = i / K, k = i - n * K;
        float v = W[(size_t)k * N + n];
        __nv_bfloat16 h = __float2bfloat16(v);
        hi[i] = h;
        lo[i] = __float2bfloat16(v - __bfloat162float(h));
    }
}

// ---------------- HMMA dual GEMM with bf16 error-split ----------------
// C = A@W + bias; A split (Ah, Al), W^T split (Bh, Bl) stored [N][K].
// CTA tile 128x128, BK=32, 8 warps of 32x64, cp.async double buffer.
// grid: (N/128, ceil(M/128), 2); z picks (Bh/Bl offset, bias, C).
constexpr int LDT = 40;                         // bf16 elems per smem row (80B)
constexpr int TILE_B = 128 * LDT * 2;           // 10240 bytes per tile
constexpr int STAGE_B = 4 * TILE_B;             // Ah,Al,Bh,Bl = 40960 bytes

__global__ void __launch_bounds__(256, 2)
k_gemm_mma(const __nv_bfloat16* __restrict__ Ah, const __nv_bfloat16* __restrict__ Al,
           const __nv_bfloat16* __restrict__ Bh, const __nv_bfloat16* __restrict__ Bl,
           const float* __restrict__ bias0, const float* __restrict__ bias1,
           float* __restrict__ C0, float* __restrict__ C1,
           int M, int N, int K) {
    extern __shared__ __align__(16) char smem[];

    const int tid  = threadIdx.x;
    const int lane = tid & 31;
    const int wid  = tid >> 5;
    const int wm   = (wid & 3) * 32;     // warp m-offset in tile
    const int wn   = (wid >> 2) * 64;    // warp n-offset in tile
    const int row0 = blockIdx.y * 128;
    const int col0 = blockIdx.x * 128;

    const __nv_bfloat16* Bh_ = Bh + (size_t)blockIdx.z * N * K;
    const __nv_bfloat16* Bl_ = Bl + (size_t)blockIdx.z * N * K;
    const float* bias = blockIdx.z ? bias1 : bias0;
    float*       C    = blockIdx.z ? C1 : C0;

    // per-thread load slots: 2 chunks of 16B per tile
    int lrow[2], lcol[2];
#pragma unroll
    for (int t = 0; t < 2; t++) {
        int c = tid + t * 256;           // 0..511
        lrow[t] = c >> 2;
        lcol[t] = (c & 3) * 8;           // bf16 col
    }

    auto load_stage = [&](int s) {
        char* sb = smem + (s & 1) * STAGE_B;
        const int k0 = s * 32;
#pragma unroll
        for (int t = 0; t < 2; t++) {
            int row = lrow[t], col = lcol[t];
            uint32_t soff = row * (LDT * 2) + col * 2;
            int ar = row0 + row;
            int az = (ar < M) ? 16 : 0;
            size_t aoff = (size_t)(az ? ar : 0) * K + k0 + col;
            cp16(sb + soff,               Ah + aoff, az);
            cp16(sb + TILE_B + soff,      Al + aoff, az);
            size_t boff = (size_t)(col0 + row) * K + k0 + col;
            cp16(sb + 2 * TILE_B + soff,  Bh_ + boff, 16);
            cp16(sb + 3 * TILE_B + soff,  Bl_ + boff, 16);
        }
        asm volatile("cp.async.commit_group;" ::: "memory");
    };

    float acc[2][8][4];
#pragma unroll
    for (int mi = 0; mi < 2; mi++)
#pragma unroll
        for (int ni = 0; ni < 8; ni++)
#pragma unroll
            for (int j = 0; j < 4; j++) acc[mi][ni][j] = 0.f;

    const int nsteps = K / 32;
    load_stage(0);

    for (int s = 0; s < nsteps; s++) {
        const bool more = (s + 1) < nsteps;
        if (more) load_stage(s + 1);
        if (more) asm volatile("cp.async.wait_group 1;" ::: "memory");
        else      asm volatile("cp.async.wait_group 0;" ::: "memory");
        __syncthreads();

        char* sb = smem + (s & 1) * STAGE_B;
        uint32_t uA  = smem_to_u32(sb);
        uint32_t uAl = uA + TILE_B;
        uint32_t uB  = uA + 2 * TILE_B;
        uint32_t uBl = uA + 3 * TILE_B;

#pragma unroll
        for (int ks = 0; ks < 2; ks++) {
            const int kc = ks * 16;
            // A fragments: lanes 0-15 rows m..m+15 @k, lanes 16-31 same rows @k+8
            uint32_t fAh[2][4], fAl[2][4];
            {
                int arow = wm + (lane & 15);
                int acol = kc + (lane >> 4) * 8;
#pragma unroll
                for (int mi = 0; mi < 2; mi++) {
                    uint32_t ad = (arow + mi * 16) * (LDT * 2) + acol * 2;
                    ldsm_x4(fAh[mi], uA  + ad);
                    ldsm_x4(fAl[mi], uAl + ad);
                }
            }
            // B fragments: 4 groups of n16 covering 64 n
            uint32_t fBh[4][4], fBl[4][4];
            {
                int brow = (lane & 7) + ((lane >> 4) & 1) * 8;
                int bcol = kc + ((lane >> 3) & 1) * 8;
#pragma unroll
                for (int g = 0; g < 4; g++) {
                    uint32_t bd = (wn + g * 16 + brow) * (LDT * 2) + bcol * 2;
                    ldsm_x4(fBh[g], uB  + bd);
                    ldsm_x4(fBl[g], uBl + bd);
                }
            }
#pragma unroll
            for (int mi = 0; mi < 2; mi++)
#pragma unroll
                for (int ni = 0; ni < 8; ni++) {
                    const uint32_t* bh = &fBh[ni >> 1][(ni & 1) * 2];
                    const uint32_t* bl = &fBl[ni >> 1][(ni & 1) * 2];
                    mma_bf16(acc[mi][ni], fAh[mi], bh);
                    mma_bf16(acc[mi][ni], fAh[mi], bl);
                    mma_bf16(acc[mi][ni], fAl[mi], bh);
                }
        }
        __syncthreads();
    }

    // epilogue: bias + store
    const int g  = lane >> 2;
    const int tg = lane & 3;
#pragma unroll
    for (int mi = 0; mi < 2; mi++) {
        int r0 = row0 + wm + mi * 16 + g;
        int r1 = r0 + 8;
#pragma unroll
        for (int ni = 0; ni < 8; ni++) {
            int cc = col0 + wn + ni * 8 + tg * 2;
            float b0 = bias[cc], b1 = bias[cc + 1];
            if (r0 < M) {
                float2 o = make_float2(acc[mi][ni][0] + b0, acc[mi][ni][1] + b1);
                *(float2*)&C[(size_t)r0 * N + cc] = o;
            }
            if (r1 < M) {
                float2 o = make_float2(acc[mi][ni][2] + b0, acc[mi][ni][3] + b1);
                *(float2*)&C[(size_t)r1 * N + cc] = o;
            }
        }
    }
}

// ---------------- per-dst-node GATv2 aggregation ----------------
template <int H, int C, bool DO_ELU>
__global__ void __launch_bounds__(128)
k_gat_aggregate(const float* __restrict__ ew,
                const int*   __restrict__ srcArr,
                const float* __restrict__ We,
                const float* __restrict__ att,
                const float* __restrict__ bias,
                float* __restrict__ out) {
    constexpr int HC  = H * C;
    constexpr int T   = 128;
    constexpr int VPT = HC / T;
    constexpr int MAXDEG = 1024;

    __shared__ float sh_xr[HC];
    __shared__ float sh_We[HC];
    __shared__ float sh_att[HC];
    __shared__ float sh_l[MAXDEG * H];
    __shared__ float sh_red[4];

    const int nd  = blockIdx.x;
    const int tid = threadIdx.x;
    const int chb = tid * VPT;
    const int h   = chb / C;

    for (int i = tid; i < HC; i += T) {
        sh_xr[i]  = g_XR[(size_t)nd * HC + i];
        sh_We[i]  = We[i];
        sh_att[i] = att[i];
    }
    __syncthreads();

    int s0  = g_start[nd];
    int deg = g_start[nd + 1] - s0;
    if (deg > MAXDEG) deg = MAXDEG;

    for (int eo = 0; eo < deg; eo++) {
        int   e = g_csr[s0 + eo];
        int   s = srcArr[e];
        float w = ew[e];
        const float* xlrow = &g_XL[(size_t)s * HC + chb];

        float xv[VPT];
        if constexpr (VPT == 4) {
            float4 v = *(const float4*)xlrow;
            xv[0] = v.x; xv[1] = v.y; xv[2] = v.z; xv[3] = v.w;
        } else {
            float2 v = *(const float2*)xlrow;
            xv[0] = v.x; xv[1] = v.y;
        }

        float partial = 0.f;
#pragma unroll
        for (int j = 0; j < VPT; j++) {
            float v = xv[j] + sh_xr[chb + j] + w * sh_We[chb + j];
            v = (v > 0.f) ? v : 0.2f * v;
            partial += v * sh_att[chb + j];
        }
#pragma unroll
        for (int off = 16; off; off >>= 1)
            partial += __shfl_xor_sync(0xffffffff, partial, off);

        if constexpr (H == 4) {
            if ((tid & 31) == 0) sh_l[eo * H + h] = partial;
        } else {
            if ((tid & 31) == 0) sh_red[tid >> 5] = partial;
            __syncthreads();
            if (tid == 0) sh_l[eo] = sh_red[0] + sh_red[1] + sh_red[2] + sh_red[3];
            __syncthreads();
        }
    }
    __syncthreads();

    if (tid < H) {
        float m = -INFINITY;
        for (int eo = 0; eo < deg; eo++) m = fmaxf(m, sh_l[eo * H + tid]);
        float ssum = 0.f;
        for (int eo = 0; eo < deg; eo++) {
            float p = expf(sh_l[eo * H + tid] - m);
            sh_l[eo * H + tid] = p;
            ssum += p;
        }
        float inv = 1.f / (ssum + 1e-16f);
        for (int eo = 0; eo < deg; eo++) sh_l[eo * H + tid] *= inv;
    }
    __syncthreads();

    float acc[VPT] = {};
    for (int eo = 0; eo < deg; eo++) {
        int   e = g_csr[s0 + eo];
        int   s = srcArr[e];
        float a = sh_l[eo * H + h];
        const float* xlrow = &g_XL[(size_t)s * HC + chb];
        if constexpr (VPT == 4) {
            float4 v = *(const float4*)xlrow;
            acc[0] += a * v.x; acc[1] += a * v.y; acc[2] += a * v.z; acc[3] += a * v.w;
        } else {
            float2 v = *(const float2*)xlrow;
            acc[0] += a * v.x; acc[1] += a * v.y;
        }
    }

#pragma unroll
    for (int j = 0; j < VPT; j++) {
        float o = acc[j] + bias[chb + j];
        if constexpr (DO_ELU) o = (o > 0.f) ? o : expm1f(o);
        out[(size_t)nd * HC + chb + j] = o;
    }
}

// ---------------- launch ----------------
extern "C" void kernel_launch(void* const* d_in, const int* in_sizes, int n_in,
                              void* d_out, int out_size) {
    const float* x   = (const float*)d_in[0];
    const int*   ei  = (const int*)  d_in[1];
    const float* ew  = (const float*)d_in[2];
    const int* src = ei;
    const int* dst = ei + NE;

    const float *Wl[3], *bl[3], *Wr[3], *br[3], *We[3], *att[3], *bias[3];
    for (int l = 0; l < 3; l++) {
        int b = 3 + 7 * l;
        Wl[l]   = (const float*)d_in[b + 0];
        bl[l]   = (const float*)d_in[b + 1];
        Wr[l]   = (const float*)d_in[b + 2];
        br[l]   = (const float*)d_in[b + 3];
        We[l]   = (const float*)d_in[b + 4];
        att[l]  = (const float*)d_in[b + 5];
        bias[l] = (const float*)d_in[b + 6];
    }

    float *dXL, *dXR, *dH;
    __nv_bfloat16 *dAh, *dAl, *dBh, *dBl;
    cudaGetSymbolAddress((void**)&dXL, g_XL);
    cudaGetSymbolAddress((void**)&dXR, g_XR);
    cudaGetSymbolAddress((void**)&dH,  g_H);
    cudaGetSymbolAddress((void**)&dAh, g_Ah);
    cudaGetSymbolAddress((void**)&dAl, g_Al);
    cudaGetSymbolAddress((void**)&dBh, g_Bh);
    cudaGetSymbolAddress((void**)&dBl, g_Bl);
    float* dOut = (float*)d_out;

    static const int SMEM_DYN = 2 * STAGE_B;   // 81920
    cudaFuncSetAttribute(k_gemm_mma, cudaFuncAttributeMaxDynamicSharedMemorySize, SMEM_DYN);

    // CSR by destination
    k_zero_deg<<<(NT + 255) / 256, 256>>>();
    k_hist    <<<(NE + 255) / 256, 256>>>(dst);
    k_scan    <<<1, 256>>>();
    k_scatter <<<(NE + 255) / 256, 256>>>(dst);

    const int MB = (NT + 127) / 128;   // 79

    // ---------- layer 0: K=64 -> N=512 ----------
    {
        const int K = 64, N = 512;
        k_split <<<(NT * K + 255) / 256, 256>>>(x, dAh, dAl, NT * K);
        k_splitW<<<(N * K + 255) / 256, 256>>>(Wl[0], dBh,         dBl,         K, N);
        k_splitW<<<(N * K + 255) / 256, 256>>>(Wr[0], dBh + N * K, dBl + N * K, K, N);
        k_gemm_mma<<<dim3(N / 128, MB, 2), 256, SMEM_DYN>>>(dAh, dAl, dBh, dBl,
                                                            bl[0], br[0], dXL, dXR, NT, N, K);
        k_gat_aggregate<4, 128, true><<<NT, 128>>>(ew, src, We[0], att[0], bias[0], dH);
    }
    // ---------- layer 1: K=512 -> N=512 ----------
    {
        const int K = 512, N = 512;
        k_split <<<(NT * K + 255) / 256, 256>>>(dH, dAh, dAl, NT * K);
        k_splitW<<<(N * K + 255) / 256, 256>>>(Wl[1], dBh,         dBl,         K, N);
        k_splitW<<<(N * K + 255) / 256, 256>>>(Wr[1], dBh + N * K, dBl + N * K, K, N);
        k_gemm_mma<<<dim3(N / 128, MB, 2), 256, SMEM_DYN>>>(dAh, dAl, dBh, dBl,
                                                            bl[1], br[1], dXL, dXR, NT, N, K);
        k_gat_aggregate<4, 128, true><<<NT, 128>>>(ew, src, We[1], att[1], bias[1], dH);
    }
    // ---------- layer 2: K=512 -> N=256 ----------
    {
        const int K = 512, N = 256;
        k_split <<<(NT * K + 255) / 256, 256>>>(dH, dAh, dAl, NT * K);
        k_splitW<<<(N * K + 255) / 256, 256>>>(Wl[2], dBh,         dBl,         K, N);
        k_splitW<<<(N * K + 255) / 256, 256>>>(Wr[2], dBh + N * K, dBl + N * K, K, N);
        k_gemm_mma<<<dim3(N / 128, MB, 2), 256, SMEM_DYN>>>(dAh, dAl, dBh, dBl,
                                                            bl[2], br[2], dXL, dXR, NT, N, K);
        k_gat_aggregate<1, 256, false><<<NT, 128>>>(ew, src, We[2], att[2], bias[2], dOut);
    }
}

// round 5
// speedup vs baseline: 2.3004x; 1.4495x over previous
#include <cuda_runtime.h>
#include <cuda_bf16.h>
#include <math.h>
#include <cstdint>

// ---------------- problem constants ----------------
#define NT 10000      // total nodes
#define NE 120000     // edges
#define HCMAX 512

// ---------------- device scratch ----------------
__device__ float g_XL[NT * HCMAX];
__device__ float g_XR[NT * HCMAX];
__device__ __nv_bfloat16 g_Ah[NT * HCMAX];
__device__ __nv_bfloat16 g_Al[NT * HCMAX];
__device__ __nv_bfloat16 g_Bh[2 * 512 * 512];   // [z][N][K] transposed weights (hi)
__device__ __nv_bfloat16 g_Bl[2 * 512 * 512];   // (lo)
__device__ int   g_deg[NT];
__device__ int   g_start[NT + 1];
__device__ int   g_cursor[NT];
__device__ int   g_csr[NE];

// ---------------- helpers ----------------
__device__ __forceinline__ uint32_t smem_to_u32(const void* p) {
    uint32_t a;
    asm("{ .reg .u64 t; cvta.to.shared.u64 t, %1; cvt.u32.u64 %0, t; }" : "=r"(a) : "l"(p));
    return a;
}
__device__ __forceinline__ void cp16(void* dst, const void* src, int srcsize) {
    uint32_t d = smem_to_u32(dst);
    asm volatile("cp.async.cg.shared.global [%0], [%1], 16, %2;"
                 :: "r"(d), "l"(src), "r"(srcsize) : "memory");
}
__device__ __forceinline__ void ldsm_x4(uint32_t* r, uint32_t addr) {
    asm volatile("ldmatrix.sync.aligned.m8n8.x4.shared.b16 {%0,%1,%2,%3}, [%4];"
                 : "=r"(r[0]), "=r"(r[1]), "=r"(r[2]), "=r"(r[3]) : "r"(addr));
}
__device__ __forceinline__ void mma_bf16(float* c, const uint32_t* a, const uint32_t* b) {
    asm volatile("mma.sync.aligned.m16n8k16.row.col.f32.bf16.bf16.f32 "
                 "{%0,%1,%2,%3}, {%4,%5,%6,%7}, {%8,%9}, {%0,%1,%2,%3};"
                 : "+f"(c[0]), "+f"(c[1]), "+f"(c[2]), "+f"(c[3])
                 : "r"(a[0]), "r"(a[1]), "r"(a[2]), "r"(a[3]), "r"(b[0]), "r"(b[1]));
}

// ---------------- CSR build ----------------
__global__ void k_zero_deg() {
    int i = blockIdx.x * blockDim.x + threadIdx.x;
    if (i < NT) g_deg[i] = 0;
}
__global__ void k_hist(const int* __restrict__ dst) {
    int e = blockIdx.x * blockDim.x + threadIdx.x;
    if (e < NE) atomicAdd(&g_deg[dst[e]], 1);
}
__global__ void k_scan() {
    __shared__ int sh[256];
    const int CH = (NT + 255) / 256;
    int tid = threadIdx.x;
    int base = tid * CH;
    int s = 0;
    for (int i = 0; i < CH; i++) { int n = base + i; if (n < NT) s += g_deg[n]; }
    sh[tid] = s;
    __syncthreads();
    for (int off = 1; off < 256; off <<= 1) {
        int v = (tid >= off) ? sh[tid - off] : 0;
        __syncthreads();
        sh[tid] += v;
        __syncthreads();
    }
    int run = sh[tid] - s;
    for (int i = 0; i < CH; i++) {
        int n = base + i;
        if (n < NT) { g_start[n] = run; g_cursor[n] = run; run += g_deg[n]; }
    }
    if (tid == 255) g_start[NT] = sh[255];
}
__global__ void k_scatter(const int* __restrict__ dst) {
    int e = blockIdx.x * blockDim.x + threadIdx.x;
    if (e < NE) {
        int p = atomicAdd(&g_cursor[dst[e]], 1);
        g_csr[p] = e;
    }
}

// ---------------- fp32 -> bf16 hi/lo split (x only) ----------------
__global__ void k_split(const float* __restrict__ in, __nv_bfloat16* __restrict__ hi,
                        __nv_bfloat16* __restrict__ lo, int n) {
    int i = blockIdx.x * blockDim.x + threadIdx.x;
    if (i < n) {
        float v = in[i];
        __nv_bfloat16 h = __float2bfloat16(v);
        hi[i] = h;
        lo[i] = __float2bfloat16(v - __bfloat162float(h));
    }
}
// W [K,N] row-major -> Wt [N,K] split bf16, both Wl (y=0) and Wr (y=1)
__global__ void k_splitW2(const float* __restrict__ W0, const float* __restrict__ W1,
                          __nv_bfloat16* __restrict__ hi, __nv_bfloat16* __restrict__ lo,
                          int K, int N) {
    const float* W = blockIdx.y ? W1 : W0;
    size_t off = (size_t)blockIdx.y * N * K;
    int i = blockIdx.x * blockDim.x + threadIdx.x;
    if (i < N * K) {
        int n = i / K, k = i - n * K;
        float v = W[(size_t)k * N + n];
        __nv_bfloat16 h = __float2bfloat16(v);
        hi[off + i] = h;
        lo[off + i] = __float2bfloat16(v - __bfloat162float(h));
    }
}

// ---------------- HMMA dual GEMM with bf16 error-split ----------------
constexpr int LDT = 40;                         // bf16 elems per smem row (80B)
constexpr int TILE_B = 128 * LDT * 2;           // 10240 bytes per tile
constexpr int STAGE_B = 4 * TILE_B;             // Ah,Al,Bh,Bl = 40960 bytes

__global__ void __launch_bounds__(256, 2)
k_gemm_mma(const __nv_bfloat16* __restrict__ Ah, const __nv_bfloat16* __restrict__ Al,
           const __nv_bfloat16* __restrict__ Bh, const __nv_bfloat16* __restrict__ Bl,
           const float* __restrict__ bias0, const float* __restrict__ bias1,
           float* __restrict__ C0, float* __restrict__ C1,
           int M, int N, int K) {
    extern __shared__ __align__(16) char smem[];

    const int tid  = threadIdx.x;
    const int lane = tid & 31;
    const int wid  = tid >> 5;
    const int wm   = (wid & 3) * 32;
    const int wn   = (wid >> 2) * 64;
    const int row0 = blockIdx.y * 128;
    const int col0 = blockIdx.x * 128;

    const __nv_bfloat16* Bh_ = Bh + (size_t)blockIdx.z * N * K;
    const __nv_bfloat16* Bl_ = Bl + (size_t)blockIdx.z * N * K;
    const float* bias = blockIdx.z ? bias1 : bias0;
    float*       C    = blockIdx.z ? C1 : C0;

    int lrow[2], lcol[2];
#pragma unroll
    for (int t = 0; t < 2; t++) {
        int c = tid + t * 256;
        lrow[t] = c >> 2;
        lcol[t] = (c & 3) * 8;
    }

    auto load_stage = [&](int s) {
        char* sb = smem + (s & 1) * STAGE_B;
        const int k0 = s * 32;
#pragma unroll
        for (int t = 0; t < 2; t++) {
            int row = lrow[t], col = lcol[t];
            uint32_t soff = row * (LDT * 2) + col * 2;
            int ar = row0 + row;
            int az = (ar < M) ? 16 : 0;
            size_t aoff = (size_t)(az ? ar : 0) * K + k0 + col;
            cp16(sb + soff,               Ah + aoff, az);
            cp16(sb + TILE_B + soff,      Al + aoff, az);
            size_t boff = (size_t)(col0 + row) * K + k0 + col;
            cp16(sb + 2 * TILE_B + soff,  Bh_ + boff, 16);
            cp16(sb + 3 * TILE_B + soff,  Bl_ + boff, 16);
        }
        asm volatile("cp.async.commit_group;" ::: "memory");
    };

    float acc[2][8][4];
#pragma unroll
    for (int mi = 0; mi < 2; mi++)
#pragma unroll
        for (int ni = 0; ni < 8; ni++)
#pragma unroll
            for (int j = 0; j < 4; j++) acc[mi][ni][j] = 0.f;

    const int nsteps = K / 32;
    load_stage(0);

    for (int s = 0; s < nsteps; s++) {
        const bool more = (s + 1) < nsteps;
        if (more) load_stage(s + 1);
        if (more) asm volatile("cp.async.wait_group 1;" ::: "memory");
        else      asm volatile("cp.async.wait_group 0;" ::: "memory");
        __syncthreads();

        char* sb = smem + (s & 1) * STAGE_B;
        uint32_t uA  = smem_to_u32(sb);
        uint32_t uAl = uA + TILE_B;
        uint32_t uB  = uA + 2 * TILE_B;
        uint32_t uBl = uA + 3 * TILE_B;

#pragma unroll
        for (int ks = 0; ks < 2; ks++) {
            const int kc = ks * 16;
            uint32_t fAh[2][4], fAl[2][4];
            {
                int arow = wm + (lane & 15);
                int acol = kc + (lane >> 4) * 8;
#pragma unroll
                for (int mi = 0; mi < 2; mi++) {
                    uint32_t ad = (arow + mi * 16) * (LDT * 2) + acol * 2;
                    ldsm_x4(fAh[mi], uA  + ad);
                    ldsm_x4(fAl[mi], uAl + ad);
                }
            }
            uint32_t fBh[4][4], fBl[4][4];
            {
                int brow = (lane & 7) + ((lane >> 4) & 1) * 8;
                int bcol = kc + ((lane >> 3) & 1) * 8;
#pragma unroll
                for (int g = 0; g < 4; g++) {
                    uint32_t bd = (wn + g * 16 + brow) * (LDT * 2) + bcol * 2;
                    ldsm_x4(fBh[g], uB  + bd);
                    ldsm_x4(fBl[g], uBl + bd);
                }
            }
#pragma unroll
            for (int mi = 0; mi < 2; mi++)
#pragma unroll
                for (int ni = 0; ni < 8; ni++) {
                    const uint32_t* bh = &fBh[ni >> 1][(ni & 1) * 2];
                    const uint32_t* bl = &fBl[ni >> 1][(ni & 1) * 2];
                    mma_bf16(acc[mi][ni], fAh[mi], bh);
                    mma_bf16(acc[mi][ni], fAh[mi], bl);
                    mma_bf16(acc[mi][ni], fAl[mi], bh);
                }
        }
        __syncthreads();
    }

    const int g  = lane >> 2;
    const int tg = lane & 3;
#pragma unroll
    for (int mi = 0; mi < 2; mi++) {
        int r0 = row0 + wm + mi * 16 + g;
        int r1 = r0 + 8;
#pragma unroll
        for (int ni = 0; ni < 8; ni++) {
            int cc = col0 + wn + ni * 8 + tg * 2;
            float b0 = bias[cc], b1 = bias[cc + 1];
            if (r0 < M) {
                float2 o = make_float2(acc[mi][ni][0] + b0, acc[mi][ni][1] + b1);
                *(float2*)&C[(size_t)r0 * N + cc] = o;
            }
            if (r1 < M) {
                float2 o = make_float2(acc[mi][ni][2] + b0, acc[mi][ni][3] + b1);
                *(float2*)&C[(size_t)r1 * N + cc] = o;
            }
        }
    }
}

// ---------------- warp-per-(node,head) GATv2 aggregation, online softmax ----------------
// H==4: block=128, one node per block, warp w = head w, lane covers 4 channels (float4).
// H==1: block=128, 4 nodes per block (one per warp), lane covers 8 channels (2x float4).
// Single gather of xl per edge; logit + weighted accum fused via online softmax.
// Epilogue: +bias, optional ELU, then either fp32 store or fused bf16 hi/lo split.
template <int H, int C, bool DO_ELU, bool SPLIT_OUT>
__global__ void __launch_bounds__(128)
k_gat_agg(const float* __restrict__ ew,
          const int*   __restrict__ srcArr,
          const float* __restrict__ We,
          const float* __restrict__ att,
          const float* __restrict__ bias,
          float* __restrict__ outF,
          __nv_bfloat16* __restrict__ outH,
          __nv_bfloat16* __restrict__ outL) {
    constexpr int HC  = H * C;
    constexpr int VPT = C / 32;           // 4 (H=4) or 8 (H=1)

    const int wid  = threadIdx.x >> 5;
    const int lane = threadIdx.x & 31;

    int nd, h;
    if constexpr (H == 4) { nd = blockIdx.x; h = wid; }
    else                  { nd = blockIdx.x * 4 + wid; h = 0; if (nd >= NT) return; }
    const int chb = h * C + lane * VPT;

    float rxr[VPT], rWe[VPT], ratt[VPT];
#pragma unroll
    for (int j = 0; j < VPT; j += 4) {
        *(float4*)&rxr[j]  = *(const float4*)&g_XR[(size_t)nd * HC + chb + j];
        *(float4*)&rWe[j]  = *(const float4*)&We[chb + j];
        *(float4*)&ratt[j] = *(const float4*)&att[chb + j];
    }

    const int s0  = g_start[nd];
    const int deg = g_start[nd + 1] - s0;

    float m = -INFINITY, ssum = 0.f;
    float acc[VPT];
#pragma unroll
    for (int j = 0; j < VPT; j++) acc[j] = 0.f;

    int   sN = 0;
    float wN = 0.f;
    if (deg > 0) { int e = g_csr[s0]; sN = srcArr[e]; wN = ew[e]; }

    for (int eo = 0; eo < deg; eo++) {
        const int   s = sN;
        const float w = wN;
        if (eo + 1 < deg) { int e2 = g_csr[s0 + eo + 1]; sN = srcArr[e2]; wN = ew[e2]; }

        const float* xp = &g_XL[(size_t)s * HC + chb];
        float xv[VPT];
#pragma unroll
        for (int j = 0; j < VPT; j += 4)
            *(float4*)&xv[j] = *(const float4*)(xp + j);

        float partial = 0.f;
#pragma unroll
        for (int j = 0; j < VPT; j++) {
            float v = xv[j] + rxr[j] + w * rWe[j];
            v = (v > 0.f) ? v : 0.2f * v;        // leaky_relu(0.2)
            partial += v * ratt[j];
        }
#pragma unroll
        for (int off = 16; off; off >>= 1)
            partial += __shfl_xor_sync(0xffffffff, partial, off);
        const float l = partial;

        const float mnew  = fmaxf(m, l);
        const float scale = __expf(m - mnew);
        const float p     = __expf(l - mnew);
        ssum = ssum * scale + p;
#pragma unroll
        for (int j = 0; j < VPT; j++)
            acc[j] = acc[j] * scale + p * xv[j];
        m = mnew;
    }

    const float inv = 1.f / (ssum + 1e-16f);
    const size_t ob = (size_t)nd * HC + chb;
#pragma unroll
    for (int j = 0; j < VPT; j++) {
        float o = acc[j] * inv + bias[chb + j];
        if constexpr (DO_ELU) o = (o > 0.f) ? o : expm1f(o);
        if constexpr (SPLIT_OUT) {
            __nv_bfloat16 hh = __float2bfloat16(o);
            outH[ob + j] = hh;
            outL[ob + j] = __float2bfloat16(o - __bfloat162float(hh));
        } else {
            outF[ob + j] = o;
        }
    }
}

// ---------------- launch ----------------
extern "C" void kernel_launch(void* const* d_in, const int* in_sizes, int n_in,
                              void* d_out, int out_size) {
    const float* x   = (const float*)d_in[0];
    const int*   ei  = (const int*)  d_in[1];
    const float* ew  = (const float*)d_in[2];
    const int* src = ei;
    const int* dst = ei + NE;

    const float *Wl[3], *bl[3], *Wr[3], *br[3], *We[3], *att[3], *bias[3];
    for (int l = 0; l < 3; l++) {
        int b = 3 + 7 * l;
        Wl[l]   = (const float*)d_in[b + 0];
        bl[l]   = (const float*)d_in[b + 1];
        Wr[l]   = (const float*)d_in[b + 2];
        br[l]   = (const float*)d_in[b + 3];
        We[l]   = (const float*)d_in[b + 4];
        att[l]  = (const float*)d_in[b + 5];
        bias[l] = (const float*)d_in[b + 6];
    }

    float *dXL, *dXR;
    __nv_bfloat16 *dAh, *dAl, *dBh, *dBl;
    cudaGetSymbolAddress((void**)&dXL, g_XL);
    cudaGetSymbolAddress((void**)&dXR, g_XR);
    cudaGetSymbolAddress((void**)&dAh, g_Ah);
    cudaGetSymbolAddress((void**)&dAl, g_Al);
    cudaGetSymbolAddress((void**)&dBh, g_Bh);
    cudaGetSymbolAddress((void**)&dBl, g_Bl);
    float* dOut = (float*)d_out;

    static const int SMEM_DYN = 2 * STAGE_B;   // 81920
    cudaFuncSetAttribute(k_gemm_mma, cudaFuncAttributeMaxDynamicSharedMemorySize, SMEM_DYN);

    // CSR by destination
    k_zero_deg<<<(NT + 255) / 256, 256>>>();
    k_hist    <<<(NE + 255) / 256, 256>>>(dst);
    k_scan    <<<1, 256>>>();
    k_scatter <<<(NE + 255) / 256, 256>>>(dst);

    const int MB = (NT + 127) / 128;   // 79

    // ---------- layer 0: K=64 -> N=512 ----------
    {
        const int K = 64, N = 512;
        k_split  <<<(NT * K + 255) / 256, 256>>>(x, dAh, dAl, NT * K);
        k_splitW2<<<dim3((N * K + 255) / 256, 2), 256>>>(Wl[0], Wr[0], dBh, dBl, K, N);
        k_gemm_mma<<<dim3(N / 128, MB, 2), 256, SMEM_DYN>>>(dAh, dAl, dBh, dBl,
                                                            bl[0], br[0], dXL, dXR, NT, N, K);
        k_gat_agg<4, 128, true, true><<<NT, 128>>>(ew, src, We[0], att[0], bias[0],
                                                   nullptr, dAh, dAl);
    }
    // ---------- layer 1: K=512 -> N=512 ----------
    {
        const int K = 512, N = 512;
        k_splitW2<<<dim3((N * K + 255) / 256, 2), 256>>>(Wl[1], Wr[1], dBh, dBl, K, N);
        k_gemm_mma<<<dim3(N / 128, MB, 2), 256, SMEM_DYN>>>(dAh, dAl, dBh, dBl,
                                                            bl[1], br[1], dXL, dXR, NT, N, K);
        k_gat_agg<4, 128, true, true><<<NT, 128>>>(ew, src, We[1], att[1], bias[1],
                                                   nullptr, dAh, dAl);
    }
    // ---------- layer 2: K=512 -> N=256 ----------
    {
        const int K = 512, N = 256;
        k_splitW2<<<dim3((N * K + 255) / 256, 2), 256>>>(Wl[2], Wr[2], dBh, dBl, K, N);
        k_gemm_mma<<<dim3(N / 128, MB, 2), 256, SMEM_DYN>>>(dAh, dAl, dBh, dBl,
                                                            bl[2], br[2], dXL, dXR, NT, N, K);
        k_gat_agg<1, 256, false, false><<<(NT + 3) / 4, 128>>>(ew, src, We[2], att[2], bias[2],
                                                               dOut, nullptr, nullptr);
    }
}

// round 6
// speedup vs baseline: 2.4526x; 1.0661x over previous
#include <cuda_runtime.h>
#include <cuda.h>
#include <cuda_bf16.h>
#include <math.h>
#include <cstdint>

// ---------------- problem constants ----------------
#define NT 10000      // total nodes
#define NE 120000     // edges
#define HCMAX 512

// ---------------- device scratch ----------------
__device__ float g_XL[NT * HCMAX];
__device__ float g_XR[NT * HCMAX];
__device__ __nv_bfloat16 g_Ah[NT * HCMAX];
__device__ __nv_bfloat16 g_Al[NT * HCMAX];
__device__ __nv_bfloat16 g_Bh[2 * 512 * 512];   // [z][N][K] transposed weights (hi)
__device__ __nv_bfloat16 g_Bl[2 * 512 * 512];   // (lo)
__device__ int   g_deg[NT];
__device__ int   g_start[NT + 1];
__device__ int   g_cursor[NT];
__device__ int   g_csr[NE];

// ---------------- device helpers ----------------
__device__ __forceinline__ uint32_t smem_to_u32(const void* p) {
    uint32_t a;
    asm("{ .reg .u64 t; cvta.to.shared.u64 t, %1; cvt.u32.u64 %0, t; }" : "=r"(a) : "l"(p));
    return a;
}
__device__ __forceinline__ void ldsm_x4(uint32_t* r, uint32_t addr) {
    asm volatile("ldmatrix.sync.aligned.m8n8.x4.shared.b16 {%0,%1,%2,%3}, [%4];"
                 : "=r"(r[0]), "=r"(r[1]), "=r"(r[2]), "=r"(r[3]) : "r"(addr));
}
__device__ __forceinline__ void mma_bf16(float* c, const uint32_t* a, const uint32_t* b) {
    asm volatile("mma.sync.aligned.m16n8k16.row.col.f32.bf16.bf16.f32 "
                 "{%0,%1,%2,%3}, {%4,%5,%6,%7}, {%8,%9}, {%0,%1,%2,%3};"
                 : "+f"(c[0]), "+f"(c[1]), "+f"(c[2]), "+f"(c[3])
                 : "r"(a[0]), "r"(a[1]), "r"(a[2]), "r"(a[3]), "r"(b[0]), "r"(b[1]));
}
__device__ __forceinline__ void tma2d(uint32_t smem, const CUtensorMap* m, int x, int y, uint32_t mb) {
    asm volatile("cp.async.bulk.tensor.2d.shared::cta.global.tile.mbarrier::complete_tx::bytes "
                 "[%0], [%1, {%2, %3}], [%4];"
                 :: "r"(smem), "l"(m), "r"(x), "r"(y), "r"(mb) : "memory");
}
__device__ __forceinline__ void mbar_init(uint32_t mb, uint32_t cnt) {
    asm volatile("mbarrier.init.shared.b64 [%0], %1;" :: "r"(mb), "r"(cnt) : "memory");
}
__device__ __forceinline__ void mbar_expect(uint32_t mb, uint32_t bytes) {
    asm volatile("mbarrier.arrive.expect_tx.shared.b64 _, [%0], %1;" :: "r"(mb), "r"(bytes) : "memory");
}
__device__ __forceinline__ void mbar_wait(uint32_t mb, uint32_t par) {
    uint32_t done;
    asm volatile("{ .reg .pred p; mbarrier.try_wait.parity.acquire.cta.shared::cta.b64 p, [%1], %2;"
                 " selp.b32 %0, 1, 0, p; }" : "=r"(done) : "r"(mb), "r"(par) : "memory");
    if (!done) {
        asm volatile("{ .reg .pred P1; WL_%=: mbarrier.try_wait.parity.acquire.cta.shared::cta.b64 P1, [%0], %1, 0x989680;"
                     " @P1 bra.uni WD_%=; bra.uni WL_%=; WD_%=: }"
                     :: "r"(mb), "r"(par) : "memory");
    }
}
// SW64 swizzle: XOR 16B-chunk index with (row>>1)&3 pattern
__device__ __forceinline__ uint32_t sw64(uint32_t o) { return o ^ ((o >> 3) & 0x30); }

// ---------------- CSR build ----------------
__global__ void k_zero_deg() {
    int i = blockIdx.x * blockDim.x + threadIdx.x;
    if (i < NT) g_deg[i] = 0;
}
__global__ void k_hist(const int* __restrict__ dst) {
    int e = blockIdx.x * blockDim.x + threadIdx.x;
    if (e < NE) atomicAdd(&g_deg[dst[e]], 1);
}
__global__ void k_scan() {
    __shared__ int sh[256];
    const int CH = (NT + 255) / 256;
    int tid = threadIdx.x;
    int base = tid * CH;
    int s = 0;
    for (int i = 0; i < CH; i++) { int n = base + i; if (n < NT) s += g_deg[n]; }
    sh[tid] = s;
    __syncthreads();
    for (int off = 1; off < 256; off <<= 1) {
        int v = (tid >= off) ? sh[tid - off] : 0;
        __syncthreads();
        sh[tid] += v;
        __syncthreads();
    }
    int run = sh[tid] - s;
    for (int i = 0; i < CH; i++) {
        int n = base + i;
        if (n < NT) { g_start[n] = run; g_cursor[n] = run; run += g_deg[n]; }
    }
    if (tid == 255) g_start[NT] = sh[255];
}
__global__ void k_scatter(const int* __restrict__ dst) {
    int e = blockIdx.x * blockDim.x + threadIdx.x;
    if (e < NE) {
        int p = atomicAdd(&g_cursor[dst[e]], 1);
        g_csr[p] = e;
    }
}

// ---------------- fp32 -> bf16 hi/lo split ----------------
__global__ void k_split(const float* __restrict__ in, __nv_bfloat16* __restrict__ hi,
                        __nv_bfloat16* __restrict__ lo, int n) {
    int i = blockIdx.x * blockDim.x + threadIdx.x;
    if (i < n) {
        float v = in[i];
        __nv_bfloat16 h = __float2bfloat16(v);
        hi[i] = h;
        lo[i] = __float2bfloat16(v - __bfloat162float(h));
    }
}
__global__ void k_splitW2(const float* __restrict__ W0, const float* __restrict__ W1,
                          __nv_bfloat16* __restrict__ hi, __nv_bfloat16* __restrict__ lo,
                          int K, int N) {
    const float* W = blockIdx.y ? W1 : W0;
    size_t off = (size_t)blockIdx.y * N * K;
    int i = blockIdx.x * blockDim.x + threadIdx.x;
    if (i < N * K) {
        int n = i / K, k = i - n * K;
        float v = W[(size_t)k * N + n];
        __nv_bfloat16 h = __float2bfloat16(v);
        hi[off + i] = h;
        lo[off + i] = __float2bfloat16(v - __bfloat162float(h));
    }
}

// ---------------- TMA-fed HMMA dual GEMM with bf16 error-split ----------------
// CTA tile 128x128, BK=32, 3-stage TMA pipeline, 8 warps of 32x64.
// smem stage: Ah[128x32] Al Bh Bl, each 128 rows x 64B (SW64 swizzled) = 8KB -> 32KB/stage.
constexpr int TILE_SZ  = 128 * 64;         // 8192 B
constexpr int STAGE_SZ = 4 * TILE_SZ;      // 32768 B
constexpr int NSTAGE   = 3;
constexpr int GEMM_DYN = NSTAGE * STAGE_SZ + 1024 + 64;   // stages + align slack + mbarriers

__global__ void __launch_bounds__(256, 2)
k_gemm_tma(const __grid_constant__ CUtensorMap tAh, const __grid_constant__ CUtensorMap tAl,
           const __grid_constant__ CUtensorMap tBh, const __grid_constant__ CUtensorMap tBl,
           const float* __restrict__ bias0, const float* __restrict__ bias1,
           float* __restrict__ C0, float* __restrict__ C1,
           int M, int N, int K) {
    extern __shared__ char smem[];
    const uint32_t sraw  = smem_to_u32(smem);
    const uint32_t sbase = (sraw + 1023u) & ~1023u;
    const uint32_t mbars = sbase + NSTAGE * STAGE_SZ;

    const int tid  = threadIdx.x;
    const int lane = tid & 31;
    const int wid  = tid >> 5;
    const int wm   = (wid & 3) * 32;
    const int wn   = (wid >> 2) * 64;
    const int row0 = blockIdx.y * 128;
    const int col0 = blockIdx.x * 128;
    const int brow = (int)blockIdx.z * N + col0;    // row into [2N, K] B tensor
    const float* bias = blockIdx.z ? bias1 : bias0;
    float*       C    = blockIdx.z ? C1 : C0;

    if (tid == 0) {
#pragma unroll
        for (int s = 0; s < NSTAGE; s++) mbar_init(mbars + s * 8, 1);
    }
    __syncthreads();

    const int nsteps = K / 32;

    auto issue = [&](int s) {
        if (tid == 0) {
            const int buf = s % NSTAGE;
            const uint32_t sb = sbase + buf * STAGE_SZ;
            const uint32_t mb = mbars + buf * 8;
            const int k0 = s * 32;
            mbar_expect(mb, STAGE_SZ);
            tma2d(sb,               &tAh, k0, row0, mb);
            tma2d(sb + TILE_SZ,     &tAl, k0, row0, mb);
            tma2d(sb + 2 * TILE_SZ, &tBh, k0, brow, mb);
            tma2d(sb + 3 * TILE_SZ, &tBl, k0, brow, mb);
        }
    };

    float acc[2][8][4];
#pragma unroll
    for (int mi = 0; mi < 2; mi++)
#pragma unroll
        for (int ni = 0; ni < 8; ni++)
#pragma unroll
            for (int j = 0; j < 4; j++) acc[mi][ni][j] = 0.f;

    issue(0);
    if (nsteps > 1) issue(1);

    int ph[NSTAGE] = {0, 0, 0};

    for (int s = 0; s < nsteps; s++) {
        const int buf = s % NSTAGE;
        mbar_wait(mbars + buf * 8, ph[buf]);
        ph[buf] ^= 1;

        const uint32_t uA  = sbase + buf * STAGE_SZ;
        const uint32_t uAl = uA + TILE_SZ;
        const uint32_t uB  = uA + 2 * TILE_SZ;
        const uint32_t uBl = uA + 3 * TILE_SZ;

#pragma unroll
        for (int ks = 0; ks < 2; ks++) {
            const int kcb = ks * 32;                 // byte offset of k-chunk
            uint32_t fAh[2][4], fAl[2][4];
            {
                const int arow = wm + (lane & 15);
                const int acb  = kcb + (lane >> 4) * 16;
#pragma unroll
                for (int mi = 0; mi < 2; mi++) {
                    uint32_t lin = (uint32_t)((arow + mi * 16) * 64 + acb);
                    uint32_t ad  = sw64(lin);
                    ldsm_x4(fAh[mi], uA  + ad);
                    ldsm_x4(fAl[mi], uAl + ad);
                }
            }
            uint32_t fBh[4][4], fBl[4][4];
            {
                const int br = (lane & 7) + ((lane >> 4) & 1) * 8;
                const int bcb = kcb + ((lane >> 3) & 1) * 16;
#pragma unroll
                for (int g = 0; g < 4; g++) {
                    uint32_t lin = (uint32_t)((wn + g * 16 + br) * 64 + bcb);
                    uint32_t ad  = sw64(lin);
                    ldsm_x4(fBh[g], uB  + ad);
                    ldsm_x4(fBl[g], uBl + ad);
                }
            }
#pragma unroll
            for (int mi = 0; mi < 2; mi++)
#pragma unroll
                for (int ni = 0; ni < 8; ni++) {
                    const uint32_t* bh = &fBh[ni >> 1][(ni & 1) * 2];
                    const uint32_t* bl = &fBl[ni >> 1][(ni & 1) * 2];
                    mma_bf16(acc[mi][ni], fAh[mi], bh);
                    mma_bf16(acc[mi][ni], fAh[mi], bl);
                    mma_bf16(acc[mi][ni], fAl[mi], bh);
                }
        }
        __syncthreads();
        if (s + 2 < nsteps) issue(s + 2);
    }

    // epilogue: bias + store
    const int g  = lane >> 2;
    const int tg = lane & 3;
#pragma unroll
    for (int mi = 0; mi < 2; mi++) {
        int r0 = row0 + wm + mi * 16 + g;
        int r1 = r0 + 8;
#pragma unroll
        for (int ni = 0; ni < 8; ni++) {
            int cc = col0 + wn + ni * 8 + tg * 2;
            float b0 = bias[cc], b1 = bias[cc + 1];
            if (r0 < M) {
                float2 o = make_float2(acc[mi][ni][0] + b0, acc[mi][ni][1] + b1);
                *(float2*)&C[(size_t)r0 * N + cc] = o;
            }
            if (r1 < M) {
                float2 o = make_float2(acc[mi][ni][2] + b0, acc[mi][ni][3] + b1);
                *(float2*)&C[(size_t)r1 * N + cc] = o;
            }
        }
    }
}

// ---------------- warp-per-(node,head) GATv2 aggregation, online softmax ----------------
template <int H, int C, bool DO_ELU, bool SPLIT_OUT>
__global__ void __launch_bounds__(128)
k_gat_agg(const float* __restrict__ ew,
          const int*   __restrict__ srcArr,
          const float* __restrict__ We,
          const float* __restrict__ att,
          const float* __restrict__ bias,
          float* __restrict__ outF,
          __nv_bfloat16* __restrict__ outH,
          __nv_bfloat16* __restrict__ outL) {
    constexpr int HC  = H * C;
    constexpr int VPT = C / 32;           // 4 (H=4) or 8 (H=1)

    const int wid  = threadIdx.x >> 5;
    const int lane = threadIdx.x & 31;

    int nd, h;
    if constexpr (H == 4) { nd = blockIdx.x; h = wid; }
    else                  { nd = blockIdx.x * 4 + wid; h = 0; if (nd >= NT) return; }
    const int chb = h * C + lane * VPT;

    float rxr[VPT], rWe[VPT], ratt[VPT];
#pragma unroll
    for (int j = 0; j < VPT; j += 4) {
        *(float4*)&rxr[j]  = *(const float4*)&g_XR[(size_t)nd * HC + chb + j];
        *(float4*)&rWe[j]  = *(const float4*)&We[chb + j];
        *(float4*)&ratt[j] = *(const float4*)&att[chb + j];
    }

    const int s0  = g_start[nd];
    const int deg = g_start[nd + 1] - s0;

    float m = -INFINITY, ssum = 0.f;
    float acc[VPT];
#pragma unroll
    for (int j = 0; j < VPT; j++) acc[j] = 0.f;

    int   sN = 0;
    float wN = 0.f;
    if (deg > 0) { int e = g_csr[s0]; sN = srcArr[e]; wN = ew[e]; }

    for (int eo = 0; eo < deg; eo++) {
        const int   s = sN;
        const float w = wN;
        if (eo + 1 < deg) { int e2 = g_csr[s0 + eo + 1]; sN = srcArr[e2]; wN = ew[e2]; }

        const float* xp = &g_XL[(size_t)s * HC + chb];
        float xv[VPT];
#pragma unroll
        for (int j = 0; j < VPT; j += 4)
            *(float4*)&xv[j] = *(const float4*)(xp + j);

        float partial = 0.f;
#pragma unroll
        for (int j = 0; j < VPT; j++) {
            float v = xv[j] + rxr[j] + w * rWe[j];
            v = (v > 0.f) ? v : 0.2f * v;        // leaky_relu(0.2)
            partial += v * ratt[j];
        }
#pragma unroll
        for (int off = 16; off; off >>= 1)
            partial += __shfl_xor_sync(0xffffffff, partial, off);
        const float l = partial;

        const float mnew  = fmaxf(m, l);
        const float scale = __expf(m - mnew);
        const float p     = __expf(l - mnew);
        ssum = ssum * scale + p;
#pragma unroll
        for (int j = 0; j < VPT; j++)
            acc[j] = acc[j] * scale + p * xv[j];
        m = mnew;
    }

    const float inv = 1.f / (ssum + 1e-16f);
    const size_t ob = (size_t)nd * HC + chb;
#pragma unroll
    for (int j = 0; j < VPT; j++) {
        float o = acc[j] * inv + bias[chb + j];
        if constexpr (DO_ELU) o = (o > 0.f) ? o : expm1f(o);
        if constexpr (SPLIT_OUT) {
            __nv_bfloat16 hh = __float2bfloat16(o);
            outH[ob + j] = hh;
            outL[ob + j] = __float2bfloat16(o - __bfloat162float(hh));
        } else {
            outF[ob + j] = o;
        }
    }
}

// ---------------- host: tensor-map encode via runtime entry point ----------------
typedef CUresult (*EncodeFn)(CUtensorMap*, CUtensorMapDataType, cuuint32_t, void*,
                             const cuuint64_t*, const cuuint64_t*, const cuuint32_t*,
                             const cuuint32_t*, CUtensorMapInterleave, CUtensorMapSwizzle,
                             CUtensorMapL2promotion, CUtensorMapFloatOOBfill);

static EncodeFn get_encode_fn() {
    static EncodeFn fn = nullptr;
    if (!fn) {
        cudaDriverEntryPointQueryResult st;
        cudaGetDriverEntryPoint("cuTensorMapEncodeTiled", (void**)&fn, cudaEnableDefault, &st);
    }
    return fn;
}

static void make2d(CUtensorMap* m, void* ptr, int K, int rows) {
    cuuint64_t dims[2]    = {(cuuint64_t)K, (cuuint64_t)rows};
    cuuint64_t strides[1] = {(cuuint64_t)K * 2};
    cuuint32_t box[2]     = {32, 128};
    cuuint32_t es[2]      = {1, 1};
    get_encode_fn()(m, CU_TENSOR_MAP_DATA_TYPE_BFLOAT16, 2, ptr, dims, strides, box, es,
                    CU_TENSOR_MAP_INTERLEAVE_NONE, CU_TENSOR_MAP_SWIZZLE_64B,
                    CU_TENSOR_MAP_L2_PROMOTION_L2_128B, CU_TENSOR_MAP_FLOAT_OOB_FILL_NONE);
}

// ---------------- launch ----------------
extern "C" void kernel_launch(void* const* d_in, const int* in_sizes, int n_in,
                              void* d_out, int out_size) {
    const float* x   = (const float*)d_in[0];
    const int*   ei  = (const int*)  d_in[1];
    const float* ew  = (const float*)d_in[2];
    const int* src = ei;
    const int* dst = ei + NE;

    const float *Wl[3], *bl[3], *Wr[3], *br[3], *We[3], *att[3], *bias[3];
    for (int l = 0; l < 3; l++) {
        int b = 3 + 7 * l;
        Wl[l]   = (const float*)d_in[b + 0];
        bl[l]   = (const float*)d_in[b + 1];
        Wr[l]   = (const float*)d_in[b + 2];
        br[l]   = (const float*)d_in[b + 3];
        We[l]   = (const float*)d_in[b + 4];
        att[l]  = (const float*)d_in[b + 5];
        bias[l] = (const float*)d_in[b + 6];
    }

    float *dXL, *dXR;
    __nv_bfloat16 *dAh, *dAl, *dBh, *dBl;
    cudaGetSymbolAddress((void**)&dXL, g_XL);
    cudaGetSymbolAddress((void**)&dXR, g_XR);
    cudaGetSymbolAddress((void**)&dAh, g_Ah);
    cudaGetSymbolAddress((void**)&dAl, g_Al);
    cudaGetSymbolAddress((void**)&dBh, g_Bh);
    cudaGetSymbolAddress((void**)&dBl, g_Bl);
    float* dOut = (float*)d_out;

    cudaFuncSetAttribute(k_gemm_tma, cudaFuncAttributeMaxDynamicSharedMemorySize, GEMM_DYN);

    // tensor maps (CPU-only encode; device pointers are fixed __device__ symbols)
    CUtensorMap mA64h, mA64l, mA512h, mA512l;
    CUtensorMap mB0h, mB0l, mB1h, mB1l, mB2h, mB2l;
    make2d(&mA64h,  dAh, 64, NT);   make2d(&mA64l,  dAl, 64, NT);
    make2d(&mA512h, dAh, 512, NT);  make2d(&mA512l, dAl, 512, NT);
    make2d(&mB0h, dBh, 64, 2 * 512);  make2d(&mB0l, dBl, 64, 2 * 512);
    make2d(&mB1h, dBh, 512, 2 * 512); make2d(&mB1l, dBl, 512, 2 * 512);
    make2d(&mB2h, dBh, 512, 2 * 256); make2d(&mB2l, dBl, 512, 2 * 256);

    const int MB = (NT + 127) / 128;   // 79

    // Launch order arranged so the 6th launch is the layer-0 GEMM (ncu -s 5 -c 1).
    k_split  <<<(NT * 64 + 255) / 256, 256>>>(x, dAh, dAl, NT * 64);                     // 1
    k_splitW2<<<dim3((512 * 64 + 255) / 256, 2), 256>>>(Wl[0], Wr[0], dBh, dBl, 64, 512); // 2
    k_zero_deg<<<(NT + 255) / 256, 256>>>();                                             // 3
    k_hist    <<<(NE + 255) / 256, 256>>>(dst);                                          // 4
    k_scan    <<<1, 256>>>();                                                            // 5

    // ---------- layer 0: K=64 -> N=512 ----------
    k_gemm_tma<<<dim3(512 / 128, MB, 2), 256, GEMM_DYN>>>(mA64h, mA64l, mB0h, mB0l,      // 6
                                                          bl[0], br[0], dXL, dXR, NT, 512, 64);
    k_scatter<<<(NE + 255) / 256, 256>>>(dst);                                           // 7
    k_gat_agg<4, 128, true, true><<<NT, 128>>>(ew, src, We[0], att[0], bias[0],          // 8
                                               nullptr, dAh, dAl);

    // ---------- layer 1: K=512 -> N=512 ----------
    k_splitW2<<<dim3((512 * 512 + 255) / 256, 2), 256>>>(Wl[1], Wr[1], dBh, dBl, 512, 512);
    k_gemm_tma<<<dim3(512 / 128, MB, 2), 256, GEMM_DYN>>>(mA512h, mA512l, mB1h, mB1l,
                                                          bl[1], br[1], dXL, dXR, NT, 512, 512);
    k_gat_agg<4, 128, true, true><<<NT, 128>>>(ew, src, We[1], att[1], bias[1],
                                               nullptr, dAh, dAl);

    // ---------- layer 2: K=512 -> N=256 ----------
    k_splitW2<<<dim3((256 * 512 + 255) / 256, 2), 256>>>(Wl[2], Wr[2], dBh, dBl, 512, 256);
    k_gemm_tma<<<dim3(256 / 128, MB, 2), 256, GEMM_DYN>>>(mA512h, mA512l, mB2h, mB2l,
                                                          bl[2], br[2], dXL, dXR, NT, 256, 512);
    k_gat_agg<1, 256, false, false><<<(NT + 3) / 4, 128>>>(ew, src, We[2], att[2], bias[2],
                                                           dOut, nullptr, nullptr);
}

// round 7
// speedup vs baseline: 2.5722x; 1.0488x over previous
#include <cuda_runtime.h>
#include <cuda.h>
#include <cuda_bf16.h>
#include <math.h>
#include <cstdint>

// ---------------- problem constants ----------------
#define NT 10000      // total nodes
#define NE 120000     // edges
#define HCMAX 512

// per-layer weight-buffer offsets (elements) in g_Bh/g_Bl
#define WOFF0 0                 // layer0: 2*512*64  = 65536
#define WOFF1 65536             // layer1: 2*512*512 = 524288
#define WOFF2 589824            // layer2: 2*256*512 = 262144
#define WTOT  851968

// ---------------- device scratch ----------------
__device__ float g_XL[NT * HCMAX];
__device__ float g_XR[NT * HCMAX];
__device__ __nv_bfloat16 g_Ah[NT * HCMAX];
__device__ __nv_bfloat16 g_Al[NT * HCMAX];
__device__ __nv_bfloat16 g_Bh[WTOT];
__device__ __nv_bfloat16 g_Bl[WTOT];
__device__ int   g_deg[NT];
__device__ int   g_start[NT + 1];
__device__ int   g_cursor[NT];
__device__ int   g_csr[NE];

// ---------------- device helpers ----------------
__device__ __forceinline__ uint32_t smem_to_u32(const void* p) {
    uint32_t a;
    asm("{ .reg .u64 t; cvta.to.shared.u64 t, %1; cvt.u32.u64 %0, t; }" : "=r"(a) : "l"(p));
    return a;
}
__device__ __forceinline__ void ldsm_x4(uint32_t* r, uint32_t addr) {
    asm volatile("ldmatrix.sync.aligned.m8n8.x4.shared.b16 {%0,%1,%2,%3}, [%4];"
                 : "=r"(r[0]), "=r"(r[1]), "=r"(r[2]), "=r"(r[3]) : "r"(addr));
}
__device__ __forceinline__ void mma_bf16(float* c, const uint32_t* a, const uint32_t* b) {
    asm volatile("mma.sync.aligned.m16n8k16.row.col.f32.bf16.bf16.f32 "
                 "{%0,%1,%2,%3}, {%4,%5,%6,%7}, {%8,%9}, {%0,%1,%2,%3};"
                 : "+f"(c[0]), "+f"(c[1]), "+f"(c[2]), "+f"(c[3])
                 : "r"(a[0]), "r"(a[1]), "r"(a[2]), "r"(a[3]), "r"(b[0]), "r"(b[1]));
}
__device__ __forceinline__ void tma2d(uint32_t smem, const CUtensorMap* m, int x, int y, uint32_t mb) {
    asm volatile("cp.async.bulk.tensor.2d.shared::cta.global.tile.mbarrier::complete_tx::bytes "
                 "[%0], [%1, {%2, %3}], [%4];"
                 :: "r"(smem), "l"(m), "r"(x), "r"(y), "r"(mb) : "memory");
}
__device__ __forceinline__ void mbar_init(uint32_t mb, uint32_t cnt) {
    asm volatile("mbarrier.init.shared.b64 [%0], %1;" :: "r"(mb), "r"(cnt) : "memory");
}
__device__ __forceinline__ void mbar_expect(uint32_t mb, uint32_t bytes) {
    asm volatile("mbarrier.arrive.expect_tx.shared.b64 _, [%0], %1;" :: "r"(mb), "r"(bytes) : "memory");
}
__device__ __forceinline__ void mbar_wait(uint32_t mb, uint32_t par) {
    uint32_t done;
    asm volatile("{ .reg .pred p; mbarrier.try_wait.parity.acquire.cta.shared::cta.b64 p, [%1], %2;"
                 " selp.b32 %0, 1, 0, p; }" : "=r"(done) : "r"(mb), "r"(par) : "memory");
    if (!done) {
        asm volatile("{ .reg .pred P1; WL_%=: mbarrier.try_wait.parity.acquire.cta.shared::cta.b64 P1, [%0], %1, 0x989680;"
                     " @P1 bra.uni WD_%=; bra.uni WL_%=; WD_%=: }"
                     :: "r"(mb), "r"(par) : "memory");
    }
}
__device__ __forceinline__ uint32_t sw64(uint32_t o) { return o ^ ((o >> 3) & 0x30); }

// ---------------- CSR build ----------------
__global__ void k_zero_deg() {
    int i = blockIdx.x * blockDim.x + threadIdx.x;
    if (i < NT) g_deg[i] = 0;
}
__global__ void k_hist(const int* __restrict__ dst) {
    int e = blockIdx.x * blockDim.x + threadIdx.x;
    if (e < NE) atomicAdd(&g_deg[dst[e]], 1);
}
__global__ void k_scan() {
    __shared__ int sh[256];
    const int CH = (NT + 255) / 256;
    int tid = threadIdx.x;
    int base = tid * CH;
    int s = 0;
    for (int i = 0; i < CH; i++) { int n = base + i; if (n < NT) s += g_deg[n]; }
    sh[tid] = s;
    __syncthreads();
    for (int off = 1; off < 256; off <<= 1) {
        int v = (tid >= off) ? sh[tid - off] : 0;
        __syncthreads();
        sh[tid] += v;
        __syncthreads();
    }
    int run = sh[tid] - s;
    for (int i = 0; i < CH; i++) {
        int n = base + i;
        if (n < NT) { g_start[n] = run; g_cursor[n] = run; run += g_deg[n]; }
    }
    if (tid == 255) g_start[NT] = sh[255];
}
__global__ void k_scatter(const int* __restrict__ dst) {
    int e = blockIdx.x * blockDim.x + threadIdx.x;
    if (e < NE) {
        int p = atomicAdd(&g_cursor[dst[e]], 1);
        g_csr[p] = e;
    }
}

// ---------------- fp32 -> bf16 hi/lo split ----------------
__global__ void k_split(const float* __restrict__ in, __nv_bfloat16* __restrict__ hi,
                        __nv_bfloat16* __restrict__ lo, int n) {
    int i = blockIdx.x * blockDim.x + threadIdx.x;
    if (i < n) {
        float v = in[i];
        __nv_bfloat16 h = __float2bfloat16(v);
        hi[i] = h;
        lo[i] = __float2bfloat16(v - __bfloat162float(h));
    }
}
__global__ void k_splitW2(const float* __restrict__ W0, const float* __restrict__ W1,
                          __nv_bfloat16* __restrict__ hi, __nv_bfloat16* __restrict__ lo,
                          int K, int N) {
    const float* W = blockIdx.y ? W1 : W0;
    size_t off = (size_t)blockIdx.y * N * K;
    int i = blockIdx.x * blockDim.x + threadIdx.x;
    if (i < N * K) {
        int n = i / K, k = i - n * K;
        float v = W[(size_t)k * N + n];
        __nv_bfloat16 h = __float2bfloat16(v);
        hi[off + i] = h;
        lo[off + i] = __float2bfloat16(v - __bfloat162float(h));
    }
}

// ---------------- TMA-fed HMMA dual GEMM with bf16 error-split ----------------
constexpr int TILE_SZ  = 128 * 64;         // 8192 B
constexpr int STAGE_SZ = 4 * TILE_SZ;      // 32768 B
constexpr int NSTAGE   = 3;
constexpr int GEMM_DYN = NSTAGE * STAGE_SZ + 1024 + 64;

__global__ void __launch_bounds__(256, 2)
k_gemm_tma(const __grid_constant__ CUtensorMap tAh, const __grid_constant__ CUtensorMap tAl,
           const __grid_constant__ CUtensorMap tBh, const __grid_constant__ CUtensorMap tBl,
           const float* __restrict__ bias0, const float* __restrict__ bias1,
           float* __restrict__ C0, float* __restrict__ C1,
           int M, int N, int K) {
    extern __shared__ char smem[];
    const uint32_t sraw  = smem_to_u32(smem);
    const uint32_t sbase = (sraw + 1023u) & ~1023u;
    const uint32_t mbars = sbase + NSTAGE * STAGE_SZ;

    const int tid  = threadIdx.x;
    const int lane = tid & 31;
    const int wid  = tid >> 5;
    const int wm   = (wid & 3) * 32;
    const int wn   = (wid >> 2) * 64;
    const int row0 = blockIdx.y * 128;
    const int col0 = blockIdx.x * 128;
    const int brow = (int)blockIdx.z * N + col0;
    const float* bias = blockIdx.z ? bias1 : bias0;
    float*       C    = blockIdx.z ? C1 : C0;

    if (tid == 0) {
#pragma unroll
        for (int s = 0; s < NSTAGE; s++) mbar_init(mbars + s * 8, 1);
    }
    __syncthreads();

    const int nsteps = K / 32;

    auto issue = [&](int s) {
        if (tid == 0) {
            const int buf = s % NSTAGE;
            const uint32_t sb = sbase + buf * STAGE_SZ;
            const uint32_t mb = mbars + buf * 8;
            const int k0 = s * 32;
            mbar_expect(mb, STAGE_SZ);
            tma2d(sb,               &tAh, k0, row0, mb);
            tma2d(sb + TILE_SZ,     &tAl, k0, row0, mb);
            tma2d(sb + 2 * TILE_SZ, &tBh, k0, brow, mb);
            tma2d(sb + 3 * TILE_SZ, &tBl, k0, brow, mb);
        }
    };

    float acc[2][8][4];
#pragma unroll
    for (int mi = 0; mi < 2; mi++)
#pragma unroll
        for (int ni = 0; ni < 8; ni++)
#pragma unroll
            for (int j = 0; j < 4; j++) acc[mi][ni][j] = 0.f;

    issue(0);
    if (nsteps > 1) issue(1);

    int ph[NSTAGE] = {0, 0, 0};

    for (int s = 0; s < nsteps; s++) {
        const int buf = s % NSTAGE;
        mbar_wait(mbars + buf * 8, ph[buf]);
        ph[buf] ^= 1;

        const uint32_t uA  = sbase + buf * STAGE_SZ;
        const uint32_t uAl = uA + TILE_SZ;
        const uint32_t uB  = uA + 2 * TILE_SZ;
        const uint32_t uBl = uA + 3 * TILE_SZ;

#pragma unroll
        for (int ks = 0; ks < 2; ks++) {
            const int kcb = ks * 32;
            uint32_t fAh[2][4], fAl[2][4];
            {
                const int arow = wm + (lane & 15);
                const int acb  = kcb + (lane >> 4) * 16;
#pragma unroll
                for (int mi = 0; mi < 2; mi++) {
                    uint32_t lin = (uint32_t)((arow + mi * 16) * 64 + acb);
                    uint32_t ad  = sw64(lin);
                    ldsm_x4(fAh[mi], uA  + ad);
                    ldsm_x4(fAl[mi], uAl + ad);
                }
            }
            uint32_t fBh[4][4], fBl[4][4];
            {
                const int br = (lane & 7) + ((lane >> 4) & 1) * 8;
                const int bcb = kcb + ((lane >> 3) & 1) * 16;
#pragma unroll
                for (int g = 0; g < 4; g++) {
                    uint32_t lin = (uint32_t)((wn + g * 16 + br) * 64 + bcb);
                    uint32_t ad  = sw64(lin);
                    ldsm_x4(fBh[g], uB  + ad);
                    ldsm_x4(fBl[g], uBl + ad);
                }
            }
#pragma unroll
            for (int mi = 0; mi < 2; mi++)
#pragma unroll
                for (int ni = 0; ni < 8; ni++) {
                    const uint32_t* bh = &fBh[ni >> 1][(ni & 1) * 2];
                    const uint32_t* bl = &fBl[ni >> 1][(ni & 1) * 2];
                    mma_bf16(acc[mi][ni], fAh[mi], bh);
                    mma_bf16(acc[mi][ni], fAh[mi], bl);
                    mma_bf16(acc[mi][ni], fAl[mi], bh);
                }
        }
        __syncthreads();
        if (s + 2 < nsteps) issue(s + 2);
    }

    const int g  = lane >> 2;
    const int tg = lane & 3;
#pragma unroll
    for (int mi = 0; mi < 2; mi++) {
        int r0 = row0 + wm + mi * 16 + g;
        int r1 = r0 + 8;
#pragma unroll
        for (int ni = 0; ni < 8; ni++) {
            int cc = col0 + wn + ni * 8 + tg * 2;
            float b0 = bias[cc], b1 = bias[cc + 1];
            if (r0 < M) {
                float2 o = make_float2(acc[mi][ni][0] + b0, acc[mi][ni][1] + b1);
                *(float2*)&C[(size_t)r0 * N + cc] = o;
            }
            if (r1 < M) {
                float2 o = make_float2(acc[mi][ni][2] + b0, acc[mi][ni][3] + b1);
                *(float2*)&C[(size_t)r1 * N + cc] = o;
            }
        }
    }
}

// ---------------- warp-per-(node,head) GATv2 aggregation, online softmax ----------------
template <int H, int C, bool DO_ELU, bool SPLIT_OUT>
__global__ void __launch_bounds__(128)
k_gat_agg(const float* __restrict__ ew,
          const int*   __restrict__ srcArr,
          const float* __restrict__ We,
          const float* __restrict__ att,
          const float* __restrict__ bias,
          float* __restrict__ outF,
          __nv_bfloat16* __restrict__ outH,
          __nv_bfloat16* __restrict__ outL) {
    constexpr int HC  = H * C;
    constexpr int VPT = C / 32;

    const int wid  = threadIdx.x >> 5;
    const int lane = threadIdx.x & 31;

    int nd, h;
    if constexpr (H == 4) { nd = blockIdx.x; h = wid; }
    else                  { nd = blockIdx.x * 4 + wid; h = 0; if (nd >= NT) return; }
    const int chb = h * C + lane * VPT;

    float rxr[VPT], rWe[VPT], ratt[VPT];
#pragma unroll
    for (int j = 0; j < VPT; j += 4) {
        *(float4*)&rxr[j]  = *(const float4*)&g_XR[(size_t)nd * HC + chb + j];
        *(float4*)&rWe[j]  = *(const float4*)&We[chb + j];
        *(float4*)&ratt[j] = *(const float4*)&att[chb + j];
    }

    const int s0  = g_start[nd];
    const int deg = g_start[nd + 1] - s0;

    float m = -INFINITY, ssum = 0.f;
    float acc[VPT];
#pragma unroll
    for (int j = 0; j < VPT; j++) acc[j] = 0.f;

    int   sN = 0;
    float wN = 0.f;
    if (deg > 0) { int e = g_csr[s0]; sN = srcArr[e]; wN = ew[e]; }

    for (int eo = 0; eo < deg; eo++) {
        const int   s = sN;
        const float w = wN;
        if (eo + 1 < deg) { int e2 = g_csr[s0 + eo + 1]; sN = srcArr[e2]; wN = ew[e2]; }

        const float* xp = &g_XL[(size_t)s * HC + chb];
        float xv[VPT];
#pragma unroll
        for (int j = 0; j < VPT; j += 4)
            *(float4*)&xv[j] = *(const float4*)(xp + j);

        float partial = 0.f;
#pragma unroll
        for (int j = 0; j < VPT; j++) {
            float v = xv[j] + rxr[j] + w * rWe[j];
            v = (v > 0.f) ? v : 0.2f * v;
            partial += v * ratt[j];
        }
#pragma unroll
        for (int off = 16; off; off >>= 1)
            partial += __shfl_xor_sync(0xffffffff, partial, off);
        const float l = partial;

        const float mnew  = fmaxf(m, l);
        const float scale = __expf(m - mnew);
        const float p     = __expf(l - mnew);
        ssum = ssum * scale + p;
#pragma unroll
        for (int j = 0; j < VPT; j++)
            acc[j] = acc[j] * scale + p * xv[j];
        m = mnew;
    }

    const float inv = 1.f / (ssum + 1e-16f);
    const size_t ob = (size_t)nd * HC + chb;
#pragma unroll
    for (int j = 0; j < VPT; j++) {
        float o = acc[j] * inv + bias[chb + j];
        if constexpr (DO_ELU) o = (o > 0.f) ? o : expm1f(o);
        if constexpr (SPLIT_OUT) {
            __nv_bfloat16 hh = __float2bfloat16(o);
            outH[ob + j] = hh;
            outL[ob + j] = __float2bfloat16(o - __bfloat162float(hh));
        } else {
            outF[ob + j] = o;
        }
    }
}

// ---------------- host: tensor-map encode via runtime entry point ----------------
typedef CUresult (*EncodeFn)(CUtensorMap*, CUtensorMapDataType, cuuint32_t, void*,
                             const cuuint64_t*, const cuuint64_t*, const cuuint32_t*,
                             const cuuint32_t*, CUtensorMapInterleave, CUtensorMapSwizzle,
                             CUtensorMapL2promotion, CUtensorMapFloatOOBfill);

static EncodeFn get_encode_fn() {
    static EncodeFn fn = nullptr;
    if (!fn) {
        cudaDriverEntryPointQueryResult st;
        cudaGetDriverEntryPoint("cuTensorMapEncodeTiled", (void**)&fn, cudaEnableDefault, &st);
    }
    return fn;
}

static void make2d(CUtensorMap* m, void* ptr, int K, int rows) {
    cuuint64_t dims[2]    = {(cuuint64_t)K, (cuuint64_t)rows};
    cuuint64_t strides[1] = {(cuuint64_t)K * 2};
    cuuint32_t box[2]     = {32, 128};
    cuuint32_t es[2]      = {1, 1};
    get_encode_fn()(m, CU_TENSOR_MAP_DATA_TYPE_BFLOAT16, 2, ptr, dims, strides, box, es,
                    CU_TENSOR_MAP_INTERLEAVE_NONE, CU_TENSOR_MAP_SWIZZLE_64B,
                    CU_TENSOR_MAP_L2_PROMOTION_L2_128B, CU_TENSOR_MAP_FLOAT_OOB_FILL_NONE);
}

// ---------------- launch ----------------
extern "C" void kernel_launch(void* const* d_in, const int* in_sizes, int n_in,
                              void* d_out, int out_size) {
    const float* x   = (const float*)d_in[0];
    const int*   ei  = (const int*)  d_in[1];
    const float* ew  = (const float*)d_in[2];
    const int* src = ei;
    const int* dst = ei + NE;

    const float *Wl[3], *bl[3], *Wr[3], *br[3], *We[3], *att[3], *bias[3];
    for (int l = 0; l < 3; l++) {
        int b = 3 + 7 * l;
        Wl[l]   = (const float*)d_in[b + 0];
        bl[l]   = (const float*)d_in[b + 1];
        Wr[l]   = (const float*)d_in[b + 2];
        br[l]   = (const float*)d_in[b + 3];
        We[l]   = (const float*)d_in[b + 4];
        att[l]  = (const float*)d_in[b + 5];
        bias[l] = (const float*)d_in[b + 6];
    }

    float *dXL, *dXR;
    __nv_bfloat16 *dAh, *dAl, *dBh, *dBl;
    cudaGetSymbolAddress((void**)&dXL, g_XL);
    cudaGetSymbolAddress((void**)&dXR, g_XR);
    cudaGetSymbolAddress((void**)&dAh, g_Ah);
    cudaGetSymbolAddress((void**)&dAl, g_Al);
    cudaGetSymbolAddress((void**)&dBh, g_Bh);
    cudaGetSymbolAddress((void**)&dBl, g_Bl);
    float* dOut = (float*)d_out;

    cudaFuncSetAttribute(k_gemm_tma, cudaFuncAttributeMaxDynamicSharedMemorySize, GEMM_DYN);

    // one-time side stream + events (created on first, uncaptured, call)
    static cudaStream_t sside = nullptr;
    static cudaEvent_t evFork = nullptr, ev1 = nullptr, ev2 = nullptr;
    if (!sside) {
        cudaStreamCreateWithFlags(&sside, cudaStreamNonBlocking);
        cudaEventCreateWithFlags(&evFork, cudaEventDisableTiming);
        cudaEventCreateWithFlags(&ev1,    cudaEventDisableTiming);
        cudaEventCreateWithFlags(&ev2,    cudaEventDisableTiming);
    }

    // tensor maps
    CUtensorMap mA64h, mA64l, mA512h, mA512l;
    CUtensorMap mB0h, mB0l, mB1h, mB1l, mB2h, mB2l;
    make2d(&mA64h,  dAh, 64, NT);   make2d(&mA64l,  dAl, 64, NT);
    make2d(&mA512h, dAh, 512, NT);  make2d(&mA512l, dAl, 512, NT);
    make2d(&mB0h, dBh + WOFF0, 64,  2 * 512); make2d(&mB0l, dBl + WOFF0, 64,  2 * 512);
    make2d(&mB1h, dBh + WOFF1, 512, 2 * 512); make2d(&mB1l, dBl + WOFF1, 512, 2 * 512);
    make2d(&mB2h, dBh + WOFF2, 512, 2 * 256); make2d(&mB2l, dBl + WOFF2, 512, 2 * 256);

    const int MB = (NT + 127) / 128;   // 79

    // ---- fork: side stream does weight splits + CSR build concurrently ----
    cudaEventRecord(evFork, 0);
    cudaStreamWaitEvent(sside, evFork, 0);

    // side: layer-0 weights first (needed soonest), then CSR, then later weights
    k_splitW2<<<dim3((512 * 64 + 255) / 256, 2), 256, 0, sside>>>(Wl[0], Wr[0],
                                                                  dBh + WOFF0, dBl + WOFF0, 64, 512);
    cudaEventRecord(ev1, sside);
    k_zero_deg<<<(NT + 255) / 256, 256, 0, sside>>>();
    k_hist    <<<(NE + 255) / 256, 256, 0, sside>>>(dst);
    k_scan    <<<1, 256, 0, sside>>>();
    k_scatter <<<(NE + 255) / 256, 256, 0, sside>>>(dst);
    k_splitW2<<<dim3((512 * 512 + 255) / 256, 2), 256, 0, sside>>>(Wl[1], Wr[1],
                                                                   dBh + WOFF1, dBl + WOFF1, 512, 512);
    k_splitW2<<<dim3((256 * 512 + 255) / 256, 2), 256, 0, sside>>>(Wl[2], Wr[2],
                                                                   dBh + WOFF2, dBl + WOFF2, 512, 256);
    cudaEventRecord(ev2, sside);

    // main: split input, then layer chain
    k_split<<<(NT * 64 + 255) / 256, 256>>>(x, dAh, dAl, NT * 64);

    // ---------- layer 0: K=64 -> N=512 ----------
    cudaStreamWaitEvent(0, ev1, 0);
    k_gemm_tma<<<dim3(512 / 128, MB, 2), 256, GEMM_DYN>>>(mA64h, mA64l, mB0h, mB0l,
                                                          bl[0], br[0], dXL, dXR, NT, 512, 64);
    cudaStreamWaitEvent(0, ev2, 0);   // CSR + later weights ready
    k_gat_agg<4, 128, true, true><<<NT, 128>>>(ew, src, We[0], att[0], bias[0],
                                               nullptr, dAh, dAl);

    // ---------- layer 1: K=512 -> N=512 ----------
    k_gemm_tma<<<dim3(512 / 128, MB, 2), 256, GEMM_DYN>>>(mA512h, mA512l, mB1h, mB1l,
                                                          bl[1], br[1], dXL, dXR, NT, 512, 512);
    k_gat_agg<4, 128, true, true><<<NT, 128>>>(ew, src, We[1], att[1], bias[1],
                                               nullptr, dAh, dAl);

    // ---------- layer 2: K=512 -> N=256 ----------
    k_gemm_tma<<<dim3(256 / 128, MB, 2), 256, GEMM_DYN>>>(mA512h, mA512l, mB2h, mB2l,
                                                          bl[2], br[2], dXL, dXR, NT, 256, 512);
    k_gat_agg<1, 256, false, false><<<(NT + 3) / 4, 128>>>(ew, src, We[2], att[2], bias[2],
                                                           dOut, nullptr, nullptr);
}